// round 10
// baseline (speedup 1.0000x reference)
#include <cuda_runtime.h>
#include <cuda_fp16.h>
#include <cstdint>

#define NUSER 50000
#define NITEM 50000
#define NEDGE 1600000
#define D 64

#define TILE 1024
#define NTILE ((NUSER + TILE - 1) / TILE)   // 49 tiles per side

#define HIST_BLOCKS ((NEDGE + 255) / 256)           // 6250
#define CONV_BLOCKS ((2 * NUSER * D / 4 + 255) / 256) // 6250
#define FIN_BLOCKS_PER_SIDE ((NUSER + 63) / 64)     // 782
#define GEMM_BLOCKS (2 * FIN_BLOCKS_PER_SIDE)       // 1564
#define MEGA_BLOCKS (HIST_BLOCKS + CONV_BLOCKS + GEMM_BLOCKS)

// ---- Scratch (device globals; allocation is forbidden) ----
__device__ __align__(16) int g_deg_item[NITEM];
__device__ __align__(16) int g_deg_user[NUSER];
__device__ __align__(16) int g_off_item[NITEM];
__device__ __align__(16) int g_off_user[NUSER];
__device__ int g_tsum[2][NTILE];          // per-tile sums (0=item, 1=user)
__device__ int g_rank_item[NEDGE];        // rank of edge within its item bucket
__device__ int g_rank_user[NEDGE];        // rank of edge within its user bucket
__device__ int g_esrc_item[NEDGE];        // user ids, grouped by dst item
__device__ int g_esrc_user[NEDGE];        // item ids, grouped by dst user
__device__ __half g_uf_h[NUSER * D];      // user_feat in fp16 (gather table)
__device__ __half g_if_h[NITEM * D];      // item_feat in fp16 (gather table)
__device__ float g_mean_item[NITEM * D];  // mean of user_feat over in-edges
__device__ float g_mean_user[NUSER * D];  // mean of item_feat over in-edges

// ---- f32x2 packed helpers ----
__device__ __forceinline__ void ffma2(unsigned long long& d,
                                      unsigned long long a, unsigned long long b) {
    asm("fma.rn.f32x2 %0, %1, %2, %0;" : "+l"(d) : "l"(a), "l"(b));
}
__device__ __forceinline__ unsigned long long pk2(float lo, float hi) {
    unsigned long long r;
    asm("mov.b64 %0, {%1, %2};" : "=l"(r) : "f"(lo), "f"(hi));
    return r;
}
__device__ __forceinline__ unsigned long long bcast2(float x) {
    unsigned long long r;
    asm("mov.b64 %0, {%1, %1};" : "=l"(r) : "f"(x));
    return r;
}
__device__ __forceinline__ void unpk(unsigned long long v, float& lo, float& hi) {
    asm("mov.b64 {%0, %1}, %2;" : "=f"(lo), "=f"(hi) : "l"(v));
}

// ---------------------------------------------------------------------------
// Mega kernel: three independent block groups co-resident on the chip.
//   [0, HIST)            : degree histogram + edge ranks (latency-bound)
//   [HIST, HIST+CONV)    : fp32 -> fp16 feature conversion (DRAM-bound)
//   [HIST+CONV, ...)     : self-loop GEMM  out = feat @ W_loop + h_bias
// ---------------------------------------------------------------------------
__global__ void mega_kernel(const float* __restrict__ user_feat,
                            const float* __restrict__ item_feat,
                            const int* __restrict__ rate_dst,
                            const int* __restrict__ rev_dst,
                            const float* __restrict__ W_loop,
                            const float* __restrict__ h_bias,
                            float* __restrict__ out) {
    __shared__ float At[64][68];    // GEMM branch only
    __shared__ float Ws[64][68];
    __shared__ float bias_h[64];

    int b = blockIdx.x;
    const int tid = threadIdx.x;

    if (b < HIST_BLOCKS) {
        // ---- histogram ----
        int i = b * 256 + tid;
        if (i < NEDGE) {
            g_rank_item[i] = atomicAdd(&g_deg_item[__ldg(rate_dst + i)], 1);
            g_rank_user[i] = atomicAdd(&g_deg_user[__ldg(rev_dst + i)], 1);
        }
        return;
    }
    b -= HIST_BLOCKS;
    if (b < CONV_BLOCKS) {
        // ---- fp16 conversion ----
        const int n4 = NUSER * D / 4;          // 800000 per side
        int i = b * 256 + tid;
        if (i < n4) {
            float4 v = *reinterpret_cast<const float4*>(user_feat + (size_t)i * 4);
            __half2 lo = __floats2half2_rn(v.x, v.y);
            __half2 hi = __floats2half2_rn(v.z, v.w);
            uint2 p = make_uint2(*reinterpret_cast<uint32_t*>(&lo),
                                 *reinterpret_cast<uint32_t*>(&hi));
            *reinterpret_cast<uint2*>(g_uf_h + (size_t)i * 4) = p;
        } else if (i < 2 * n4) {
            int j = i - n4;
            float4 v = *reinterpret_cast<const float4*>(item_feat + (size_t)j * 4);
            __half2 lo = __floats2half2_rn(v.x, v.y);
            __half2 hi = __floats2half2_rn(v.z, v.w);
            uint2 p = make_uint2(*reinterpret_cast<uint32_t*>(&lo),
                                 *reinterpret_cast<uint32_t*>(&hi));
            *reinterpret_cast<uint2*>(g_if_h + (size_t)j * 4) = p;
        }
        return;
    }
    b -= CONV_BLOCKS;

    // ---- self-loop GEMM: out = feat @ W_loop + h_bias ----
    const float* A0;
    float* outp;
    int row0;
    if (b < FIN_BLOCKS_PER_SIDE) {
        A0 = user_feat; outp = out; row0 = b * 64;
    } else {
        A0 = item_feat; outp = out + (size_t)NUSER * D;
        row0 = (b - FIN_BLOCKS_PER_SIDE) * 64;
    }
    const int N = NUSER;
    const int tx = tid & 15, ty = tid >> 4;
    const int rb = ty * 4;

    if (tid < 64) bias_h[tid] = h_bias[tid];
    #pragma unroll
    for (int i = tid; i < 1024; i += 256) {
        int k = i >> 4, c4 = (i & 15) << 2;
        float4 w = *reinterpret_cast<const float4*>(W_loop + k * 64 + c4);
        *reinterpret_cast<float4*>(&Ws[k][c4]) = w;
    }
    #pragma unroll
    for (int i = tid; i < 1024; i += 256) {
        int r = i >> 4, k4 = (i & 15) << 2;
        int gr = row0 + r;
        float4 a = (gr < N) ? *reinterpret_cast<const float4*>(A0 + (size_t)gr * D + k4)
                            : make_float4(0.f, 0.f, 0.f, 0.f);
        At[k4 + 0][r] = a.x;
        At[k4 + 1][r] = a.y;
        At[k4 + 2][r] = a.z;
        At[k4 + 3][r] = a.w;
    }
    __syncthreads();

    unsigned long long acc[2][4];
    #pragma unroll
    for (int p = 0; p < 2; p++)
        #pragma unroll
        for (int c = 0; c < 4; c++) acc[p][c] = 0ull;

    #pragma unroll
    for (int k = 0; k < 64; k++) {
        float4 wv = *reinterpret_cast<const float4*>(&Ws[k][tx * 4]);
        float4 av = *reinterpret_cast<const float4*>(&At[k][rb]);
        unsigned long long a01 = pk2(av.x, av.y);
        unsigned long long a23 = pk2(av.z, av.w);
        unsigned long long wx = bcast2(wv.x);
        unsigned long long wy = bcast2(wv.y);
        unsigned long long wz = bcast2(wv.z);
        unsigned long long ww = bcast2(wv.w);
        ffma2(acc[0][0], a01, wx); ffma2(acc[0][1], a01, wy);
        ffma2(acc[0][2], a01, wz); ffma2(acc[0][3], a01, ww);
        ffma2(acc[1][0], a23, wx); ffma2(acc[1][1], a23, wy);
        ffma2(acc[1][2], a23, wz); ffma2(acc[1][3], a23, ww);
    }

    float rv[4][4];
    #pragma unroll
    for (int p = 0; p < 2; p++)
        #pragma unroll
        for (int c = 0; c < 4; c++)
            unpk(acc[p][c], rv[2 * p][c], rv[2 * p + 1][c]);

    #pragma unroll
    for (int i = 0; i < 4; i++) {
        int gr = row0 + rb + i;
        if (gr < N) {
            float4 r;
            r.x = rv[i][0] + bias_h[tx * 4 + 0];
            r.y = rv[i][1] + bias_h[tx * 4 + 1];
            r.z = rv[i][2] + bias_h[tx * 4 + 2];
            r.w = rv[i][3] + bias_h[tx * 4 + 3];
            *reinterpret_cast<float4*>(outp + (size_t)gr * D + tx * 4) = r;
        }
    }
}

// ---------------------------------------------------------------------------
// Scan step 1: per-tile reduction into g_tsum.
// ---------------------------------------------------------------------------
__global__ void scan1_kernel() {
    int side = blockIdx.x / NTILE;
    int tile = blockIdx.x % NTILE;
    const int n = (side == 0) ? NITEM : NUSER;
    const int* __restrict__ deg = (side == 0) ? g_deg_item : g_deg_user;
    const int tid = threadIdx.x;
    const int e0 = tile * TILE + tid * 4;

    int s = 0;
    if (e0 + 3 < n) {
        int4 v = *reinterpret_cast<const int4*>(deg + e0);
        s = v.x + v.y + v.z + v.w;
    } else {
        for (int i = e0; i < min(e0 + 4, n); i++) s += __ldg(deg + i);
    }
    #pragma unroll
    for (int o = 16; o; o >>= 1) s += __shfl_down_sync(0xffffffffu, s, o);
    __shared__ int ws[8];
    if ((tid & 31) == 0) ws[tid >> 5] = s;
    __syncthreads();
    if (tid < 8) {
        int t = ws[tid];
        #pragma unroll
        for (int o = 4; o; o >>= 1) t += __shfl_down_sync(0xffu, t, o);
        if (tid == 0) g_tsum[side][tile] = t;
    }
}

// ---------------------------------------------------------------------------
// Scan steps 2+3 merged: warp 0 re-derives the exclusive tile-base scan of
// the 49 tile sums (cheap), then the block writes its tile's offsets.
// ---------------------------------------------------------------------------
__global__ void scan23_kernel() {
    int side = blockIdx.x / NTILE;
    int tile = blockIdx.x % NTILE;
    const int n = (side == 0) ? NITEM : NUSER;
    const int* __restrict__ deg = (side == 0) ? g_deg_item : g_deg_user;
    int* __restrict__ off = (side == 0) ? g_off_item : g_off_user;
    const int tid = threadIdx.x, lane = tid & 31, wid = tid >> 5;
    const int e0 = tile * TILE + tid * 4;

    __shared__ int s_tbase;
    if (wid == 0) {
        int v0 = (lane < NTILE) ? g_tsum[side][lane] : 0;
        int v1 = (lane + 32 < NTILE) ? g_tsum[side][lane + 32] : 0;
        int s0 = v0, s1 = v1;
        #pragma unroll
        for (int o = 1; o < 32; o <<= 1) {
            int t = __shfl_up_sync(0xffffffffu, s0, o);
            if (lane >= o) s0 += t;
            int u = __shfl_up_sync(0xffffffffu, s1, o);
            if (lane >= o) s1 += u;
        }
        int tot0 = __shfl_sync(0xffffffffu, s0, 31);
        int base;
        if (tile < 32) base = __shfl_sync(0xffffffffu, s0 - v0, tile);
        else base = tot0 + __shfl_sync(0xffffffffu, s1 - v1, tile - 32);
        if (lane == 0) s_tbase = base;
    }

    int4 v = make_int4(0, 0, 0, 0);
    if (e0 + 3 < n) {
        v = *reinterpret_cast<const int4*>(deg + e0);
    } else {
        if (e0 + 0 < n) v.x = __ldg(deg + e0 + 0);
        if (e0 + 1 < n) v.y = __ldg(deg + e0 + 1);
        if (e0 + 2 < n) v.z = __ldg(deg + e0 + 2);
        if (e0 + 3 < n) v.w = __ldg(deg + e0 + 3);
    }
    int tsum = v.x + v.y + v.z + v.w;

    int p = tsum;
    #pragma unroll
    for (int o = 1; o < 32; o <<= 1) {
        int t = __shfl_up_sync(0xffffffffu, p, o);
        if (lane >= o) p += t;
    }
    __shared__ int ws[8];
    if (lane == 31) ws[wid] = p;
    __syncthreads();
    if (tid < 8) {
        int t = ws[tid];
        #pragma unroll
        for (int o = 1; o < 8; o <<= 1) {
            int u = __shfl_up_sync(0xffu, t, o);
            if (tid >= o) t += u;
        }
        ws[tid] = t;
    }
    __syncthreads();
    int excl = (wid ? ws[wid - 1] : 0) + p - tsum + s_tbase;

    int4 o4;
    o4.x = excl;
    o4.y = o4.x + v.x;
    o4.z = o4.y + v.y;
    o4.w = o4.z + v.z;
    if (e0 + 3 < n) {
        *reinterpret_cast<int4*>(off + e0) = o4;
    } else {
        if (e0 + 0 < n) off[e0 + 0] = o4.x;
        if (e0 + 1 < n) off[e0 + 1] = o4.y;
        if (e0 + 2 < n) off[e0 + 2] = o4.z;
        if (e0 + 3 < n) off[e0 + 3] = o4.w;
    }
}

// ---------------------------------------------------------------------------
// Bin edges by destination: slot = off[dst] + rank. No atomics.
// ---------------------------------------------------------------------------
__global__ void bin_kernel(const int* __restrict__ rate_src, const int* __restrict__ rate_dst,
                           const int* __restrict__ rev_src,  const int* __restrict__ rev_dst) {
    int i = blockIdx.x * blockDim.x + threadIdx.x;
    if (i < NEDGE) {
        int p = __ldg(&g_off_item[__ldg(rate_dst + i)]) + g_rank_item[i];
        g_esrc_item[p] = __ldg(rate_src + i);
        int q = __ldg(&g_off_user[__ldg(rev_dst + i)]) + g_rank_user[i];
        g_esrc_user[q] = __ldg(rev_src + i);
    }
}

// ---------------------------------------------------------------------------
// Gather-based segment mean over fp16 rows: 16 threads per dst node, each
// owns 4 halves (8B) of the 128B row. (Round-8 proven form.)
// ---------------------------------------------------------------------------
__global__ void agg_kernel(const __half* __restrict__ feat, const int* __restrict__ esrc,
                           const int* __restrict__ off, const int* __restrict__ deg,
                           float* __restrict__ mean) {
    int t = blockIdx.x * blockDim.x + threadIdx.x;
    int g = t >> 4;          // node id (grid sized exactly: nnode*16 threads)
    int lane = t & 15;
    int dgc = __ldg(deg + g);
    int start = __ldg(off + g);
    float4 acc = make_float4(0.f, 0.f, 0.f, 0.f);
    #pragma unroll 4
    for (int j = 0; j < dgc; j++) {
        int s = __ldg(esrc + start + j);
        uint2 p = *reinterpret_cast<const uint2*>(feat + (size_t)s * D + lane * 4);
        __half2 h0 = *reinterpret_cast<__half2*>(&p.x);
        __half2 h1 = *reinterpret_cast<__half2*>(&p.y);
        float2 f0 = __half22float2(h0);
        float2 f1 = __half22float2(h1);
        acc.x += f0.x; acc.y += f0.y; acc.z += f1.x; acc.w += f1.y;
    }
    float inv = (dgc > 0) ? 1.f / (float)dgc : 0.f;
    acc.x *= inv; acc.y *= inv; acc.z *= inv; acc.w *= inv;
    *reinterpret_cast<float4*>(mean + (size_t)g * D + lane * 4) = acc;
}

// ---------------------------------------------------------------------------
// Finalize (single phase): out += mean @ W_et + (deg>0 ? b_et : 0)
// (self-loop + h_bias already written by the mega kernel's GEMM branch)
// ---------------------------------------------------------------------------
__global__ void final2_kernel(const float* __restrict__ A1, const float* __restrict__ W1,
                              const float* __restrict__ bet, const int* __restrict__ deg,
                              float* __restrict__ out, int N) {
    __shared__ float At[64][68];
    __shared__ float Ws[64][68];
    __shared__ float bias_e[64];
    const int tid = threadIdx.x;
    const int tx = tid & 15, ty = tid >> 4;
    const int row0 = blockIdx.x * 64;
    const int rb = ty * 4;

    if (tid < 64) bias_e[tid] = bet[tid];
    #pragma unroll
    for (int i = tid; i < 1024; i += 256) {
        int k = i >> 4, c4 = (i & 15) << 2;
        float4 w = *reinterpret_cast<const float4*>(W1 + k * 64 + c4);
        *reinterpret_cast<float4*>(&Ws[k][c4]) = w;
    }
    #pragma unroll
    for (int i = tid; i < 1024; i += 256) {
        int r = i >> 4, k4 = (i & 15) << 2;
        int gr = row0 + r;
        float4 a = (gr < N) ? *reinterpret_cast<const float4*>(A1 + (size_t)gr * D + k4)
                            : make_float4(0.f, 0.f, 0.f, 0.f);
        At[k4 + 0][r] = a.x;
        At[k4 + 1][r] = a.y;
        At[k4 + 2][r] = a.z;
        At[k4 + 3][r] = a.w;
    }
    __syncthreads();

    unsigned long long acc[2][4];
    #pragma unroll
    for (int p = 0; p < 2; p++)
        #pragma unroll
        for (int c = 0; c < 4; c++) acc[p][c] = 0ull;

    #pragma unroll
    for (int k = 0; k < 64; k++) {
        float4 wv = *reinterpret_cast<const float4*>(&Ws[k][tx * 4]);
        float4 av = *reinterpret_cast<const float4*>(&At[k][rb]);
        unsigned long long a01 = pk2(av.x, av.y);
        unsigned long long a23 = pk2(av.z, av.w);
        unsigned long long wx = bcast2(wv.x);
        unsigned long long wy = bcast2(wv.y);
        unsigned long long wz = bcast2(wv.z);
        unsigned long long ww = bcast2(wv.w);
        ffma2(acc[0][0], a01, wx); ffma2(acc[0][1], a01, wy);
        ffma2(acc[0][2], a01, wz); ffma2(acc[0][3], a01, ww);
        ffma2(acc[1][0], a23, wx); ffma2(acc[1][1], a23, wy);
        ffma2(acc[1][2], a23, wz); ffma2(acc[1][3], a23, ww);
    }

    float rv[4][4];
    #pragma unroll
    for (int p = 0; p < 2; p++)
        #pragma unroll
        for (int c = 0; c < 4; c++)
            unpk(acc[p][c], rv[2 * p][c], rv[2 * p + 1][c]);

    #pragma unroll
    for (int i = 0; i < 4; i++) {
        int gr = row0 + rb + i;
        if (gr < N) {
            float m = (__ldg(deg + gr) > 0) ? 1.f : 0.f;
            float4* po = reinterpret_cast<float4*>(out + (size_t)gr * D + tx * 4);
            float4 r = *po;
            r.x += rv[i][0] + m * bias_e[tx * 4 + 0];
            r.y += rv[i][1] + m * bias_e[tx * 4 + 1];
            r.z += rv[i][2] + m * bias_e[tx * 4 + 2];
            r.w += rv[i][3] + m * bias_e[tx * 4 + 3];
            *po = r;
        }
    }
}

extern "C" void kernel_launch(void* const* d_in, const int* in_sizes, int n_in,
                              void* d_out, int out_size) {
    const float* user_feat = (const float*)d_in[0];
    const float* item_feat = (const float*)d_in[1];
    const int*   rate_src  = (const int*)d_in[2];
    const int*   rate_dst  = (const int*)d_in[3];
    const int*   rev_src   = (const int*)d_in[4];
    const int*   rev_dst   = (const int*)d_in[5];
    const float* W_rate    = (const float*)d_in[6];
    const float* b_rate    = (const float*)d_in[7];
    const float* W_rev     = (const float*)d_in[8];
    const float* b_rev     = (const float*)d_in[9];
    const float* W_loop    = (const float*)d_in[10];
    const float* h_bias    = (const float*)d_in[11];

    float* out      = (float*)d_out;
    float* out_user = out;
    float* out_item = out + (size_t)NUSER * D;

    int *deg_item, *deg_user, *esrc_item, *esrc_user, *off_item, *off_user;
    float *mean_item, *mean_user;
    __half *uf_h, *if_h;
    cudaGetSymbolAddress((void**)&deg_item, g_deg_item);
    cudaGetSymbolAddress((void**)&deg_user, g_deg_user);
    cudaGetSymbolAddress((void**)&off_item, g_off_item);
    cudaGetSymbolAddress((void**)&off_user, g_off_user);
    cudaGetSymbolAddress((void**)&esrc_item, g_esrc_item);
    cudaGetSymbolAddress((void**)&esrc_user, g_esrc_user);
    cudaGetSymbolAddress((void**)&mean_item, g_mean_item);
    cudaGetSymbolAddress((void**)&mean_user, g_mean_user);
    cudaGetSymbolAddress((void**)&uf_h, g_uf_h);
    cudaGetSymbolAddress((void**)&if_h, g_if_h);

    cudaMemsetAsync(deg_item, 0, NITEM * sizeof(int));
    cudaMemsetAsync(deg_user, 0, NUSER * sizeof(int));

    mega_kernel<<<MEGA_BLOCKS, 256>>>(user_feat, item_feat, rate_dst, rev_dst,
                                      W_loop, h_bias, out);

    scan1_kernel<<<2 * NTILE, 256>>>();
    scan23_kernel<<<2 * NTILE, 256>>>();

    bin_kernel<<<(NEDGE + 255) / 256, 256>>>(rate_src, rate_dst, rev_src, rev_dst);

    // item side aggregates USER features; user side aggregates ITEM features.
    agg_kernel<<<NITEM * 16 / 256, 256>>>(uf_h, esrc_item, off_item, deg_item, mean_item);
    agg_kernel<<<NUSER * 16 / 256, 256>>>(if_h, esrc_user, off_user, deg_user, mean_user);

    final2_kernel<<<(NUSER + 63) / 64, 256>>>(mean_user, W_rev, b_rev, deg_user,
                                              out_user, NUSER);
    final2_kernel<<<(NITEM + 63) / 64, 256>>>(mean_item, W_rate, b_rate, deg_item,
                                              out_item, NITEM);
}

// round 11
// speedup vs baseline: 1.6963x; 1.6963x over previous
#include <cuda_runtime.h>
#include <cuda_fp16.h>
#include <cstdint>

#define NUSER 50000
#define NITEM 50000
#define NEDGE 1600000
#define D 64

#define TILE 1024
#define NTILE ((NUSER + TILE - 1) / TILE)   // 49 tiles per side

// ---- Scratch (device globals; allocation is forbidden) ----
__device__ __align__(16) int g_deg_item[NITEM];
__device__ __align__(16) int g_deg_user[NUSER];
__device__ __align__(16) int g_off_item[NITEM];
__device__ __align__(16) int g_off_user[NUSER];
__device__ int g_tsum[2][NTILE];          // per-tile sums (0=item, 1=user)
__device__ int g_rank_item[NEDGE];        // rank of edge within its item bucket
__device__ int g_rank_user[NEDGE];        // rank of edge within its user bucket
__device__ int g_esrc_item[NEDGE];        // user ids, grouped by dst item
__device__ int g_esrc_user[NEDGE];        // item ids, grouped by dst user
__device__ __half g_uf_h[NUSER * D];      // user_feat in fp16 (gather table)
__device__ __half g_if_h[NITEM * D];      // item_feat in fp16 (gather table)
__device__ float g_mean_item[NITEM * D];  // mean of user_feat over in-edges
__device__ float g_mean_user[NUSER * D];  // mean of item_feat over in-edges

// ---- f32x2 packed helpers ----
__device__ __forceinline__ void ffma2(unsigned long long& d,
                                      unsigned long long a, unsigned long long b) {
    asm("fma.rn.f32x2 %0, %1, %2, %0;" : "+l"(d) : "l"(a), "l"(b));
}
__device__ __forceinline__ unsigned long long pk2(float lo, float hi) {
    unsigned long long r;
    asm("mov.b64 %0, {%1, %2};" : "=l"(r) : "f"(lo), "f"(hi));
    return r;
}
__device__ __forceinline__ unsigned long long bcast2(float x) {
    unsigned long long r;
    asm("mov.b64 %0, {%1, %1};" : "=l"(r) : "f"(x));
    return r;
}
__device__ __forceinline__ void unpk(unsigned long long v, float& lo, float& hi) {
    asm("mov.b64 {%0, %1}, %2;" : "=f"(lo), "=f"(hi) : "l"(v));
}

// ---------------------------------------------------------------------------
// Prep: zero degree counters AND convert both feature tables to fp16.
// Homogeneous thin kernel (no smem, few regs) — safe to fuse.
// ---------------------------------------------------------------------------
__global__ void prep_kernel(const float* __restrict__ user_feat,
                            const float* __restrict__ item_feat) {
    const int n4 = NUSER * D / 4;          // 800000 per side
    int i = blockIdx.x * blockDim.x + threadIdx.x;
    if (i < NITEM) g_deg_item[i] = 0;
    if (i < NUSER) g_deg_user[i] = 0;
    if (i < n4) {
        float4 v = *reinterpret_cast<const float4*>(user_feat + (size_t)i * 4);
        __half2 lo = __floats2half2_rn(v.x, v.y);
        __half2 hi = __floats2half2_rn(v.z, v.w);
        uint2 p = make_uint2(*reinterpret_cast<uint32_t*>(&lo),
                             *reinterpret_cast<uint32_t*>(&hi));
        *reinterpret_cast<uint2*>(g_uf_h + (size_t)i * 4) = p;
    } else if (i < 2 * n4) {
        int j = i - n4;
        float4 v = *reinterpret_cast<const float4*>(item_feat + (size_t)j * 4);
        __half2 lo = __floats2half2_rn(v.x, v.y);
        __half2 hi = __floats2half2_rn(v.z, v.w);
        uint2 p = make_uint2(*reinterpret_cast<uint32_t*>(&lo),
                             *reinterpret_cast<uint32_t*>(&hi));
        *reinterpret_cast<uint2*>(g_if_h + (size_t)j * 4) = p;
    }
}

// ---------------------------------------------------------------------------
// Degree histogram; the atomic's return value is the edge's in-bucket rank.
// ---------------------------------------------------------------------------
__global__ void hist_kernel(const int* __restrict__ rate_dst,
                            const int* __restrict__ rev_dst) {
    int i = blockIdx.x * blockDim.x + threadIdx.x;
    if (i < NEDGE) {
        g_rank_item[i] = atomicAdd(&g_deg_item[__ldg(rate_dst + i)], 1);
        g_rank_user[i] = atomicAdd(&g_deg_user[__ldg(rev_dst + i)], 1);
    }
}

// ---------------------------------------------------------------------------
// Scan step 1: per-tile reduction into g_tsum.
// ---------------------------------------------------------------------------
__global__ void scan1_kernel() {
    int side = blockIdx.x / NTILE;
    int tile = blockIdx.x % NTILE;
    const int n = (side == 0) ? NITEM : NUSER;
    const int* __restrict__ deg = (side == 0) ? g_deg_item : g_deg_user;
    const int tid = threadIdx.x;
    const int e0 = tile * TILE + tid * 4;

    int s = 0;
    if (e0 + 3 < n) {
        int4 v = *reinterpret_cast<const int4*>(deg + e0);
        s = v.x + v.y + v.z + v.w;
    } else {
        for (int i = e0; i < min(e0 + 4, n); i++) s += __ldg(deg + i);
    }
    #pragma unroll
    for (int o = 16; o; o >>= 1) s += __shfl_down_sync(0xffffffffu, s, o);
    __shared__ int ws[8];
    if ((tid & 31) == 0) ws[tid >> 5] = s;
    __syncthreads();
    if (tid < 8) {
        int t = ws[tid];
        #pragma unroll
        for (int o = 4; o; o >>= 1) t += __shfl_down_sync(0xffu, t, o);
        if (tid == 0) g_tsum[side][tile] = t;
    }
}

// ---------------------------------------------------------------------------
// Scan steps 2+3 merged: warp 0 re-derives the exclusive tile-base scan of
// the 49 tile sums (one warp, cheap), then the block writes its tile's
// offsets. Coalesced int4 in/out.
// ---------------------------------------------------------------------------
__global__ void scan23_kernel() {
    int side = blockIdx.x / NTILE;
    int tile = blockIdx.x % NTILE;
    const int n = (side == 0) ? NITEM : NUSER;
    const int* __restrict__ deg = (side == 0) ? g_deg_item : g_deg_user;
    int* __restrict__ off = (side == 0) ? g_off_item : g_off_user;
    const int tid = threadIdx.x, lane = tid & 31, wid = tid >> 5;
    const int e0 = tile * TILE + tid * 4;

    __shared__ int s_tbase;
    if (wid == 0) {
        int v0 = (lane < NTILE) ? g_tsum[side][lane] : 0;
        int v1 = (lane + 32 < NTILE) ? g_tsum[side][lane + 32] : 0;
        int s0 = v0, s1 = v1;
        #pragma unroll
        for (int o = 1; o < 32; o <<= 1) {
            int t = __shfl_up_sync(0xffffffffu, s0, o);
            if (lane >= o) s0 += t;
            int u = __shfl_up_sync(0xffffffffu, s1, o);
            if (lane >= o) s1 += u;
        }
        int tot0 = __shfl_sync(0xffffffffu, s0, 31);
        int base;
        if (tile < 32) base = __shfl_sync(0xffffffffu, s0 - v0, tile);
        else base = tot0 + __shfl_sync(0xffffffffu, s1 - v1, tile - 32);
        if (lane == 0) s_tbase = base;
    }

    int4 v = make_int4(0, 0, 0, 0);
    if (e0 + 3 < n) {
        v = *reinterpret_cast<const int4*>(deg + e0);
    } else {
        if (e0 + 0 < n) v.x = __ldg(deg + e0 + 0);
        if (e0 + 1 < n) v.y = __ldg(deg + e0 + 1);
        if (e0 + 2 < n) v.z = __ldg(deg + e0 + 2);
        if (e0 + 3 < n) v.w = __ldg(deg + e0 + 3);
    }
    int tsum = v.x + v.y + v.z + v.w;

    int p = tsum;
    #pragma unroll
    for (int o = 1; o < 32; o <<= 1) {
        int t = __shfl_up_sync(0xffffffffu, p, o);
        if (lane >= o) p += t;
    }
    __shared__ int ws[8];
    if (lane == 31) ws[wid] = p;
    __syncthreads();
    if (tid < 8) {
        int t = ws[tid];
        #pragma unroll
        for (int o = 1; o < 8; o <<= 1) {
            int u = __shfl_up_sync(0xffu, t, o);
            if (tid >= o) t += u;
        }
        ws[tid] = t;
    }
    __syncthreads();
    int excl = (wid ? ws[wid - 1] : 0) + p - tsum + s_tbase;

    int4 o4;
    o4.x = excl;
    o4.y = o4.x + v.x;
    o4.z = o4.y + v.y;
    o4.w = o4.z + v.z;
    if (e0 + 3 < n) {
        *reinterpret_cast<int4*>(off + e0) = o4;
    } else {
        if (e0 + 0 < n) off[e0 + 0] = o4.x;
        if (e0 + 1 < n) off[e0 + 1] = o4.y;
        if (e0 + 2 < n) off[e0 + 2] = o4.z;
        if (e0 + 3 < n) off[e0 + 3] = o4.w;
    }
}

// ---------------------------------------------------------------------------
// Bin edges by destination: slot = off[dst] + rank. No atomics.
// ---------------------------------------------------------------------------
__global__ void bin_kernel(const int* __restrict__ rate_src, const int* __restrict__ rate_dst,
                           const int* __restrict__ rev_src,  const int* __restrict__ rev_dst) {
    int i = blockIdx.x * blockDim.x + threadIdx.x;
    if (i < NEDGE) {
        int p = __ldg(&g_off_item[__ldg(rate_dst + i)]) + g_rank_item[i];
        g_esrc_item[p] = __ldg(rate_src + i);
        int q = __ldg(&g_off_user[__ldg(rev_dst + i)]) + g_rank_user[i];
        g_esrc_user[q] = __ldg(rev_src + i);
    }
}

// ---------------------------------------------------------------------------
// Merged gather segment-mean, BOTH sides in one grid. 16 threads per dst
// node, each owns 4 halves (8B) of the 128B fp16 row — the proven r8 form.
// ---------------------------------------------------------------------------
#define AGG_BLOCKS_PER_SIDE (NITEM * 16 / 256)   // 3125
__global__ void agg_kernel(const __half* __restrict__ uf, const __half* __restrict__ if_) {
    int b = blockIdx.x;
    const __half* feat;
    const int *esrc, *off, *deg;
    float* mean;
    if (b < AGG_BLOCKS_PER_SIDE) {
        feat = uf; esrc = g_esrc_item; off = g_off_item;
        deg = g_deg_item; mean = g_mean_item;
    } else {
        b -= AGG_BLOCKS_PER_SIDE;
        feat = if_; esrc = g_esrc_user; off = g_off_user;
        deg = g_deg_user; mean = g_mean_user;
    }
    int t = b * 256 + threadIdx.x;
    int g = t >> 4;          // node id
    int lane = t & 15;
    int dgc = __ldg(deg + g);
    int start = __ldg(off + g);
    float4 acc = make_float4(0.f, 0.f, 0.f, 0.f);
    #pragma unroll 4
    for (int j = 0; j < dgc; j++) {
        int s = __ldg(esrc + start + j);
        uint2 p = *reinterpret_cast<const uint2*>(feat + (size_t)s * D + lane * 4);
        __half2 h0 = *reinterpret_cast<__half2*>(&p.x);
        __half2 h1 = *reinterpret_cast<__half2*>(&p.y);
        float2 f0 = __half22float2(h0);
        float2 f1 = __half22float2(h1);
        acc.x += f0.x; acc.y += f0.y; acc.z += f1.x; acc.w += f1.y;
    }
    float inv = (dgc > 0) ? 1.f / (float)dgc : 0.f;
    acc.x *= inv; acc.y *= inv; acc.z *= inv; acc.w *= inv;
    *reinterpret_cast<float4*>(mean + (size_t)g * D + lane * 4) = acc;
}

// ---------------------------------------------------------------------------
// Merged fused dual GEMM finalize (both sides, side from blockIdx):
//   out = feat @ W_loop + mean @ W_et + (deg>0 ? b_et : 0) + h_bias
// Exact r8 inner code: transposed-A smem, packed f32x2 accumulate.
// ---------------------------------------------------------------------------
#define FIN_BLOCKS_PER_SIDE ((NUSER + 63) / 64)   // 782
__global__ void final_kernel(const float* __restrict__ user_feat,
                             const float* __restrict__ item_feat,
                             const float* __restrict__ W_loop,
                             const float* __restrict__ W_rate,
                             const float* __restrict__ W_rev,
                             const float* __restrict__ b_rate,
                             const float* __restrict__ b_rev,
                             const float* __restrict__ h_bias,
                             float* __restrict__ out) {
    __shared__ float At[64][68];    // At[k][row]
    __shared__ float Ws[64][68];    // Ws[k][col]
    __shared__ float bias_h[64];
    __shared__ float bias_e[64];

    int blk = blockIdx.x;
    const float *A0, *A1, *W1, *bet;
    const int* deg;
    float* outp;
    int row0;
    if (blk < FIN_BLOCKS_PER_SIDE) {
        A0 = user_feat; A1 = g_mean_user; W1 = W_rev; bet = b_rev;
        deg = g_deg_user; outp = out; row0 = blk * 64;
    } else {
        A0 = item_feat; A1 = g_mean_item; W1 = W_rate; bet = b_rate;
        deg = g_deg_item; outp = out + (size_t)NUSER * D;
        row0 = (blk - FIN_BLOCKS_PER_SIDE) * 64;
    }
    const int N = NUSER;   // both sides 50000
    const int tid = threadIdx.x;
    const int tx = tid & 15, ty = tid >> 4;
    const int rb = ty * 4;

    if (tid < 64) bias_h[tid] = h_bias[tid];
    else if (tid < 128) bias_e[tid - 64] = bet[tid - 64];

    unsigned long long acc[2][4];   // [row pair][col]
    #pragma unroll
    for (int p = 0; p < 2; p++)
        #pragma unroll
        for (int c = 0; c < 4; c++) acc[p][c] = 0ull;

    #pragma unroll
    for (int phase = 0; phase < 2; phase++) {
        const float* A = phase ? A1 : A0;
        const float* W = phase ? W1 : W_loop;
        __syncthreads();   // protect shared reuse from previous phase
        #pragma unroll
        for (int i = tid; i < 1024; i += 256) {
            int k = i >> 4, c4 = (i & 15) << 2;
            float4 w = *reinterpret_cast<const float4*>(W + k * 64 + c4);
            *reinterpret_cast<float4*>(&Ws[k][c4]) = w;
        }
        #pragma unroll
        for (int i = tid; i < 1024; i += 256) {
            int r = i >> 4, k4 = (i & 15) << 2;
            int gr = row0 + r;
            float4 a = (gr < N) ? *reinterpret_cast<const float4*>(A + (size_t)gr * D + k4)
                                : make_float4(0.f, 0.f, 0.f, 0.f);
            At[k4 + 0][r] = a.x;
            At[k4 + 1][r] = a.y;
            At[k4 + 2][r] = a.z;
            At[k4 + 3][r] = a.w;
        }
        __syncthreads();
        #pragma unroll
        for (int k = 0; k < 64; k++) {
            float4 wv = *reinterpret_cast<const float4*>(&Ws[k][tx * 4]);
            float4 av = *reinterpret_cast<const float4*>(&At[k][rb]);
            unsigned long long a01 = pk2(av.x, av.y);   // rows rb, rb+1
            unsigned long long a23 = pk2(av.z, av.w);   // rows rb+2, rb+3
            unsigned long long wx = bcast2(wv.x);
            unsigned long long wy = bcast2(wv.y);
            unsigned long long wz = bcast2(wv.z);
            unsigned long long ww = bcast2(wv.w);
            ffma2(acc[0][0], a01, wx); ffma2(acc[0][1], a01, wy);
            ffma2(acc[0][2], a01, wz); ffma2(acc[0][3], a01, ww);
            ffma2(acc[1][0], a23, wx); ffma2(acc[1][1], a23, wy);
            ffma2(acc[1][2], a23, wz); ffma2(acc[1][3], a23, ww);
        }
    }

    float rv[4][4];
    #pragma unroll
    for (int p = 0; p < 2; p++)
        #pragma unroll
        for (int c = 0; c < 4; c++)
            unpk(acc[p][c], rv[2 * p][c], rv[2 * p + 1][c]);

    #pragma unroll
    for (int i = 0; i < 4; i++) {
        int gr = row0 + rb + i;
        if (gr < N) {
            float m = (__ldg(deg + gr) > 0) ? 1.f : 0.f;
            float4 r;
            r.x = rv[i][0] + bias_h[tx * 4 + 0] + m * bias_e[tx * 4 + 0];
            r.y = rv[i][1] + bias_h[tx * 4 + 1] + m * bias_e[tx * 4 + 1];
            r.z = rv[i][2] + bias_h[tx * 4 + 2] + m * bias_e[tx * 4 + 2];
            r.w = rv[i][3] + bias_h[tx * 4 + 3] + m * bias_e[tx * 4 + 3];
            *reinterpret_cast<float4*>(outp + (size_t)gr * D + tx * 4) = r;
        }
    }
}

extern "C" void kernel_launch(void* const* d_in, const int* in_sizes, int n_in,
                              void* d_out, int out_size) {
    const float* user_feat = (const float*)d_in[0];
    const float* item_feat = (const float*)d_in[1];
    const int*   rate_src  = (const int*)d_in[2];
    const int*   rate_dst  = (const int*)d_in[3];
    const int*   rev_src   = (const int*)d_in[4];
    const int*   rev_dst   = (const int*)d_in[5];
    const float* W_rate    = (const float*)d_in[6];
    const float* b_rate    = (const float*)d_in[7];
    const float* W_rev     = (const float*)d_in[8];
    const float* b_rev     = (const float*)d_in[9];
    const float* W_loop    = (const float*)d_in[10];
    const float* h_bias    = (const float*)d_in[11];

    float* out = (float*)d_out;

    __half *uf_h, *if_h;
    cudaGetSymbolAddress((void**)&uf_h, g_uf_h);
    cudaGetSymbolAddress((void**)&if_h, g_if_h);

    prep_kernel<<<(2 * NUSER * D / 4 + 255) / 256, 256>>>(user_feat, item_feat);
    hist_kernel<<<(NEDGE + 255) / 256, 256>>>(rate_dst, rev_dst);

    scan1_kernel<<<2 * NTILE, 256>>>();
    scan23_kernel<<<2 * NTILE, 256>>>();

    bin_kernel<<<(NEDGE + 255) / 256, 256>>>(rate_src, rate_dst, rev_src, rev_dst);

    agg_kernel<<<2 * AGG_BLOCKS_PER_SIDE, 256>>>(uf_h, if_h);

    final_kernel<<<2 * FIN_BLOCKS_PER_SIDE, 256>>>(user_feat, item_feat, W_loop,
                                                   W_rate, W_rev, b_rate, b_rev,
                                                   h_bias, out);
}